// round 1
// baseline (speedup 1.0000x reference)
#include <cuda_runtime.h>

#define BATCH 8
#define C 64
#define N 4096
#define KNN 20
#define NOUT 64
#define SLOPE 0.01f
#define NEG_INF -1e30f

// Scratch (device globals: no allocation allowed)
__device__ float g_xx[BATCH * N];            // ||x_n||^2
__device__ int   g_idx[BATCH * N * KNN];     // top-K neighbor indices
__device__ float g_g[BATCH * N * NOUT];      // [b][m][o] : W1 . x_m
__device__ float g_u[BATCH * N * NOUT];      // [b][n][o] : (W2-W1) . x_n

// ---------------------------------------------------------------------------
// Kernel A: xx[b][n] = sum_c x[b][c][n]^2
// ---------------------------------------------------------------------------
__global__ void xx_kernel(const float* __restrict__ x) {
    int b = blockIdx.y;
    int n = blockIdx.x * 256 + threadIdx.x;
    const float* xb = x + (size_t)b * C * N;
    float s = 0.f;
#pragma unroll
    for (int c = 0; c < C; c++) {
        float v = xb[c * N + n];
        s = fmaf(v, v, s);
    }
    g_xx[b * N + n] = s;
}

// ---------------------------------------------------------------------------
// Kernel B: fused Gram-tile GEMM + top-K selection.
// CTA: 128 n-rows of one batch. Loops over 32 m-tiles of 128.
// GEMM: 256 threads, 8x8 micro-tile each. Scan: threads 0..127 own one row,
// maintain a 20-entry sorted top-K in registers (static indexing only).
// ---------------------------------------------------------------------------
#define BN 128
#define BM 128
#define DPAD 129
// smem floats: xn 64*128, xm 64*128, dist 128*129, xxm 128
#define KNN_SMEM_FLOATS (64 * 128 + 64 * 128 + 128 * DPAD + 128)
#define KNN_SMEM_BYTES (KNN_SMEM_FLOATS * 4)

extern __shared__ float smem[];

__global__ __launch_bounds__(256, 1) void knn_kernel(const float* __restrict__ x) {
    int b = blockIdx.y;
    int n0 = blockIdx.x * BN;
    float* xn_s  = smem;                       // [64][128]
    float* xm_s  = xn_s + 64 * 128;            // [64][128]
    float* dist_s = xm_s + 64 * 128;           // [m][n] transposed, pad 129
    float* xxm_s = dist_s + 128 * DPAD;        // [128]

    const float* xb = x + (size_t)b * C * N;
    int tid = threadIdx.x;
    int tx = tid & 15;        // m micro-tile
    int ty = tid >> 4;        // n micro-tile

    // load n-tile: xn_s[c][j]
    {
        int j = tid & 127, c0 = tid >> 7;
        for (int c = c0; c < 64; c += 2)
            xn_s[c * 128 + j] = xb[c * N + n0 + j];
    }

    float tv[KNN];
    int   ti[KNN];
#pragma unroll
    for (int k = 0; k < KNN; k++) { tv[k] = NEG_INF; ti[k] = 0; }

    for (int m0 = 0; m0 < N; m0 += BM) {
        __syncthreads();   // previous scan done; also covers xn_s on first iter
        {
            int j = tid & 127, c0 = tid >> 7;
            for (int c = c0; c < 64; c += 2)
                xm_s[c * 128 + j] = xb[c * N + m0 + j];
            if (tid < 128) xxm_s[tid] = g_xx[b * N + m0 + tid];
        }
        __syncthreads();

        // --- 128x128 tile GEMM, 8x8 per thread ---
        float acc[8][8];
#pragma unroll
        for (int i = 0; i < 8; i++)
#pragma unroll
            for (int j = 0; j < 8; j++) acc[i][j] = 0.f;

#pragma unroll 4
        for (int c = 0; c < 64; c++) {
            float4 a0 = *(const float4*)&xn_s[c * 128 + ty * 8];
            float4 a1 = *(const float4*)&xn_s[c * 128 + ty * 8 + 4];
            float4 b0 = *(const float4*)&xm_s[c * 128 + tx * 8];
            float4 b1 = *(const float4*)&xm_s[c * 128 + tx * 8 + 4];
            float av[8] = {a0.x, a0.y, a0.z, a0.w, a1.x, a1.y, a1.z, a1.w};
            float bv[8] = {b0.x, b0.y, b0.z, b0.w, b1.x, b1.y, b1.z, b1.w};
#pragma unroll
            for (int i = 0; i < 8; i++)
#pragma unroll
                for (int j = 0; j < 8; j++)
                    acc[i][j] = fmaf(av[i], bv[j], acc[i][j]);
        }

        // write score tile transposed: dist_s[m_local][n_local]
#pragma unroll
        for (int j = 0; j < 8; j++) {
            float xxv = xxm_s[tx * 8 + j];
#pragma unroll
            for (int i = 0; i < 8; i++)
                dist_s[(tx * 8 + j) * DPAD + ty * 8 + i] = 2.f * acc[i][j] - xxv;
        }
        __syncthreads();

        // --- top-K scan: thread t owns row n_local = t ---
        if (tid < 128) {
            for (int m = 0; m < 128; m++) {
                float s = dist_s[m * DPAD + tid];
                if (s > tv[KNN - 1]) {             // strict: keeps earlier index on ties
                    float v = s; int vi = m0 + m;
#pragma unroll
                    for (int k = 0; k < KNN; k++) {
                        if (v > tv[k]) {
                            float t1 = tv[k]; tv[k] = v; v = t1;
                            int   t2 = ti[k]; ti[k] = vi; vi = t2;
                        }
                    }
                }
            }
        }
    }

    if (tid < 128) {
        int n = n0 + tid;
#pragma unroll
        for (int k = 0; k < KNN; k++)
            g_idx[(b * N + n) * KNN + k] = ti[k];
    }
}

// ---------------------------------------------------------------------------
// Kernel C: g[b][m][o] = W1[o,:].x[:,m],  u[b][m][o] = (W2-W1)[o,:].x[:,m]
// 128 threads, each owns one m; W (64x128) staged in SMEM (broadcast reads).
// ---------------------------------------------------------------------------
__global__ void proj_kernel(const float* __restrict__ x, const float* __restrict__ W) {
    __shared__ float Ws[64 * 128];
    int b = blockIdx.y;
    int m = blockIdx.x * 128 + threadIdx.x;
    for (int i = threadIdx.x; i < 64 * 128; i += 128) Ws[i] = W[i];
    __syncthreads();

    const float* xb = x + (size_t)b * C * N;
    float xr[64];
#pragma unroll
    for (int c = 0; c < 64; c++) xr[c] = xb[c * N + m];

    float* gp = g_g + ((size_t)b * N + m) * NOUT;
    float* up = g_u + ((size_t)b * N + m) * NOUT;

    for (int o = 0; o < 64; o += 4) {
        float ag[4] = {0.f, 0.f, 0.f, 0.f};
        float at[4] = {0.f, 0.f, 0.f, 0.f};
#pragma unroll
        for (int q = 0; q < 4; q++) {
#pragma unroll
            for (int c4 = 0; c4 < 16; c4++) {
                float4 w1 = *(const float4*)&Ws[(o + q) * 128 + c4 * 4];
                float4 w2 = *(const float4*)&Ws[(o + q) * 128 + 64 + c4 * 4];
                ag[q] = fmaf(w1.x, xr[c4 * 4 + 0], ag[q]);
                ag[q] = fmaf(w1.y, xr[c4 * 4 + 1], ag[q]);
                ag[q] = fmaf(w1.z, xr[c4 * 4 + 2], ag[q]);
                ag[q] = fmaf(w1.w, xr[c4 * 4 + 3], ag[q]);
                at[q] = fmaf(w2.x, xr[c4 * 4 + 0], at[q]);
                at[q] = fmaf(w2.y, xr[c4 * 4 + 1], at[q]);
                at[q] = fmaf(w2.z, xr[c4 * 4 + 2], at[q]);
                at[q] = fmaf(w2.w, xr[c4 * 4 + 3], at[q]);
            }
        }
        float4 gv = make_float4(ag[0], ag[1], ag[2], ag[3]);
        float4 uv = make_float4(at[0] - ag[0], at[1] - ag[1], at[2] - ag[2], at[3] - ag[3]);
        *(float4*)&gp[o] = gv;
        *(float4*)&up[o] = uv;
    }
}

// ---------------------------------------------------------------------------
// Kernel D: out[b][o][n] = lrelu( max_k ( g[b][idx[n][k]][o] + u[b][n][o] ) )
// 1024 threads = 32 warps; warp w handles n = n0 + w; lane covers o and o+32.
// SMEM transpose for coalesced 128B output rows.
// ---------------------------------------------------------------------------
__global__ void out_kernel(float* __restrict__ out) {
    __shared__ float os[64 * 33];
    int b = blockIdx.y;
    int w = threadIdx.x >> 5, lane = threadIdx.x & 31;
    int n = blockIdx.x * 32 + w;

    const float* up = g_u + ((size_t)b * N + n) * NOUT;
    float u0 = up[lane], u1 = up[lane + 32];
    const int* ip = g_idx + ((size_t)b * N + n) * KNN;

    float best0 = NEG_INF, best1 = NEG_INF;
#pragma unroll
    for (int k = 0; k < KNN; k++) {
        int m = ip[k];
        const float* gp = g_g + ((size_t)b * N + m) * NOUT;
        best0 = fmaxf(best0, gp[lane] + u0);
        best1 = fmaxf(best1, gp[lane + 32] + u1);
    }
    // leaky-relu is monotone: lrelu(max) == max(lrelu)
    best0 = best0 >= 0.f ? best0 : SLOPE * best0;
    best1 = best1 >= 0.f ? best1 : SLOPE * best1;

    os[lane * 33 + w] = best0;
    os[(lane + 32) * 33 + w] = best1;
    __syncthreads();

    for (int i = threadIdx.x; i < 64 * 32; i += 1024) {
        int o = i >> 5, j = i & 31;
        out[((size_t)b * 64 + o) * N + blockIdx.x * 32 + j] = os[o * 33 + j];
    }
}

// ---------------------------------------------------------------------------
extern "C" void kernel_launch(void* const* d_in, const int* in_sizes, int n_in,
                              void* d_out, int out_size) {
    const float* x = (const float*)d_in[0];   // (8, 64, 4096)
    const float* W = (const float*)d_in[1];   // (64, 128)
    float* out = (float*)d_out;               // (8, 64, 4096)

    cudaFuncSetAttribute(knn_kernel, cudaFuncAttributeMaxDynamicSharedMemorySize,
                         KNN_SMEM_BYTES);

    xx_kernel<<<dim3(N / 256, BATCH), 256>>>(x);
    knn_kernel<<<dim3(N / BN, BATCH), 256, KNN_SMEM_BYTES>>>(x);
    proj_kernel<<<dim3(N / 128, BATCH), 128>>>(x, W);
    out_kernel<<<dim3(N / 32, BATCH), 1024>>>(out);
}